// round 1
// baseline (speedup 1.0000x reference)
#include <cuda_runtime.h>
#include <math.h>

#define B 64
#define T 512
#define D 128
#define H 256
#define NB 128   // blocks (each owns 2 h-columns)
#define NT 128   // threads per block (4 warps = 4 gates)

// Cross-block state: double-buffered hidden state as (val, center, radius)
__device__ float g_h[2][3][B][H];
// Precomputed x center/radius (same layout as x: [B][T][D])
__device__ float g_xm[B * T * D];
__device__ float g_xr[B * T * D];
// Monotonic grid-barrier ticket (never reset; wrap-safe signed compare)
__device__ unsigned int g_tick = 0;

__device__ __forceinline__ void fma2(unsigned long long &acc,
                                     unsigned long long x,
                                     unsigned long long w) {
    asm("fma.rn.f32x2 %0, %1, %2, %0;" : "+l"(acc) : "l"(x), "l"(w));
}

__device__ __forceinline__ float red2(unsigned long long a) {
    float lo = __uint_as_float((unsigned)(a & 0xffffffffull));
    float hi = __uint_as_float((unsigned)(a >> 32));
    return lo + hi;
}

__device__ __forceinline__ float sigf(float x) { return 1.0f / (1.0f + expf(-x)); }

__device__ __forceinline__ void imul_b(float al, float au, float bl, float bu,
                                       float &lo, float &hi) {
    float m1 = al * bl, m2 = al * bu, m3 = au * bl, m4 = au * bu;
    lo = fminf(fminf(m1, m2), fminf(m3, m4));
    hi = fmaxf(fmaxf(m1, m2), fmaxf(m3, m4));
}

// 24 packed-FMA updates for one 4-wide K chunk (12 f32x2 accumulators)
#define ACC24()                                                                  \
    do {                                                                         \
        fma2(av00, v0.x, w0.x); fma2(am00, m0.x, w0.x); fma2(ar00, r0.x, a0.x);  \
        fma2(av01, v1.x, w0.x); fma2(am01, m1.x, w0.x); fma2(ar01, r1.x, a0.x);  \
        fma2(av10, v0.x, w1.x); fma2(am10, m0.x, w1.x); fma2(ar10, r0.x, a1.x);  \
        fma2(av11, v1.x, w1.x); fma2(am11, m1.x, w1.x); fma2(ar11, r1.x, a1.x);  \
        fma2(av00, v0.y, w0.y); fma2(am00, m0.y, w0.y); fma2(ar00, r0.y, a0.y);  \
        fma2(av01, v1.y, w0.y); fma2(am01, m1.y, w0.y); fma2(ar01, r1.y, a0.y);  \
        fma2(av10, v0.y, w1.y); fma2(am10, m0.y, w1.y); fma2(ar10, r0.y, a1.y);  \
        fma2(av11, v1.y, w1.y); fma2(am11, m1.y, w1.y); fma2(ar11, r1.y, a1.y);  \
    } while (0)

__global__ void __launch_bounds__(NT, 1)
lstm_dp_kernel(const float* __restrict__ x_val, const float* __restrict__ x_lb,
               const float* __restrict__ x_ub, const float* __restrict__ W_ih,
               const float* __restrict__ W_hh, const float* __restrict__ bias,
               float* __restrict__ out) {
    // Block owns h-columns {2*bid, 2*bid+1}; gate columns g*H + (2*bid + jj)
    __shared__ __align__(16) float ws[8][384];   // [colIdx=g*2+jj][k]: k<256 -> W_hh, k>=256 -> W_ih
    __shared__ __align__(16) float aws[8][384];  // |W|
    __shared__ float bias_s[8];
    __shared__ float pre_s[3][8][B];             // [comp v,m,r][colIdx][b]
    __shared__ float c_s[3][2][B];               // cell state (val, lb, ub)

    const int tid = threadIdx.x;
    const int bid = blockIdx.x;
    const int warp = tid >> 5;    // == gate index (i,f,g,o)
    const int bq = tid & 31;      // handles batches bq and bq+32

    // ---- Prologue: stage weights, zero state, precompute x center/radius ----
    for (int i = tid; i < 8 * 384; i += NT) {
        int c = i / 384, k = i - c * 384;
        int row = (c >> 1) * H + (bid * 2 + (c & 1));
        float w = (k < H) ? W_hh[row * H + k] : W_ih[row * D + (k - H)];
        ws[c][k] = w;
        aws[c][k] = fabsf(w);
    }
    if (tid < 8) {
        int row = (tid >> 1) * H + (bid * 2 + (tid & 1));
        bias_s[tid] = bias[row];
    }
    for (int i = tid; i < 3 * 2 * B; i += NT) ((float*)c_s)[i] = 0.f;
    {
        int j0 = bid * 2;
        for (int i = tid; i < 3 * B * 2; i += NT) {
            int comp = i / (2 * B);
            int rem = i - comp * 2 * B;
            g_h[0][comp][rem >> 1][j0 + (rem & 1)] = 0.f;
        }
    }
    {
        const float4* l4 = (const float4*)x_lb;
        const float4* u4 = (const float4*)x_ub;
        float4* m4 = (float4*)g_xm;
        float4* r4 = (float4*)g_xr;
        const int n4 = B * T * D / 4;
        for (int i = bid * NT + tid; i < n4; i += NB * NT) {
            float4 l = l4[i], u = u4[i], m, r;
            m.x = 0.5f * (l.x + u.x); m.y = 0.5f * (l.y + u.y);
            m.z = 0.5f * (l.z + u.z); m.w = 0.5f * (l.w + u.w);
            r.x = 0.5f * (u.x - l.x); r.y = 0.5f * (u.y - l.y);
            r.z = 0.5f * (u.z - l.z); r.w = 0.5f * (u.w - l.w);
            m4[i] = m; r4[i] = r;
        }
    }
    // grid barrier (release-fence, ticket arrive, spin, acquire-fence/L1 flush)
    __threadfence();
    __syncthreads();
    if (tid == 0) {
        unsigned tk = atomicAdd(&g_tick, 1u);
        unsigned target = tk - (tk % NB) + NB;
        while ((int)(*(volatile unsigned*)&g_tick - target) < 0) {}
    }
    __syncthreads();
    __threadfence();

    // ---- Per-thread GEMM tile: 2 cols x 2 batches x 3 comps ----
    const int c0 = warp * 2, c1 = c0 + 1;
    const int b0 = bq, b1 = bq + 32;
    const ulonglong2* w0p = (const ulonglong2*)ws[c0];
    const ulonglong2* w1p = (const ulonglong2*)ws[c1];
    const ulonglong2* a0p = (const ulonglong2*)aws[c0];
    const ulonglong2* a1p = (const ulonglong2*)aws[c1];

    unsigned long long av00 = 0, av01 = 0, av10 = 0, av11 = 0;
    unsigned long long am00 = 0, am01 = 0, am10 = 0, am11 = 0;
    unsigned long long ar00 = 0, ar01 = 0, ar10 = 0, ar11 = 0;

    auto xpart = [&](int tt) {
        const ulonglong2* xv0 = (const ulonglong2*)(x_val + (b0 * T + tt) * D);
        const ulonglong2* xm0 = (const ulonglong2*)(g_xm + (b0 * T + tt) * D);
        const ulonglong2* xr0 = (const ulonglong2*)(g_xr + (b0 * T + tt) * D);
        const ulonglong2* xv1 = (const ulonglong2*)(x_val + (b1 * T + tt) * D);
        const ulonglong2* xm1 = (const ulonglong2*)(g_xm + (b1 * T + tt) * D);
        const ulonglong2* xr1 = (const ulonglong2*)(g_xr + (b1 * T + tt) * D);
#pragma unroll 2
        for (int q = 0; q < D / 4; ++q) {
            ulonglong2 w0 = w0p[64 + q], w1 = w1p[64 + q];
            ulonglong2 a0 = a0p[64 + q], a1 = a1p[64 + q];
            ulonglong2 v0 = xv0[q], m0 = xm0[q], r0 = xr0[q];
            ulonglong2 v1 = xv1[q], m1 = xm1[q], r1 = xr1[q];
            ACC24();
        }
    };

    xpart(0);  // x-side projection for step 0

    for (int t = 0; t < T; ++t) {
        const int buf = t & 1;
        // ---- h-side projection (K = 256) ----
        {
            const ulonglong2* hv0 = (const ulonglong2*)&g_h[buf][0][b0][0];
            const ulonglong2* hm0 = (const ulonglong2*)&g_h[buf][1][b0][0];
            const ulonglong2* hr0 = (const ulonglong2*)&g_h[buf][2][b0][0];
            const ulonglong2* hv1 = (const ulonglong2*)&g_h[buf][0][b1][0];
            const ulonglong2* hm1 = (const ulonglong2*)&g_h[buf][1][b1][0];
            const ulonglong2* hr1 = (const ulonglong2*)&g_h[buf][2][b1][0];
#pragma unroll 2
            for (int q = 0; q < H / 4; ++q) {
                ulonglong2 w0 = w0p[q], w1 = w1p[q];
                ulonglong2 a0 = a0p[q], a1 = a1p[q];
                ulonglong2 v0 = hv0[q], m0 = hm0[q], r0 = hr0[q];
                ulonglong2 v1 = hv1[q], m1 = hm1[q], r1 = hr1[q];
                ACC24();
            }
        }
        // ---- dump accumulators, reset ----
        pre_s[0][c0][b0] = red2(av00); pre_s[0][c0][b1] = red2(av01);
        pre_s[0][c1][b0] = red2(av10); pre_s[0][c1][b1] = red2(av11);
        pre_s[1][c0][b0] = red2(am00); pre_s[1][c0][b1] = red2(am01);
        pre_s[1][c1][b0] = red2(am10); pre_s[1][c1][b1] = red2(am11);
        pre_s[2][c0][b0] = red2(ar00); pre_s[2][c0][b1] = red2(ar01);
        pre_s[2][c1][b0] = red2(ar10); pre_s[2][c1][b1] = red2(ar11);
        av00 = av01 = av10 = av11 = 0;
        am00 = am01 = am10 = am11 = 0;
        ar00 = ar01 = ar10 = ar11 = 0;
        __syncthreads();

        // ---- elementwise: one (jj, b) pair per thread ----
        {
            const int jj = tid >> 6, bb = tid & 63;
            float pv[4], pl[4], pu[4];
#pragma unroll
            for (int g = 0; g < 4; ++g) {
                int c = g * 2 + jj;
                float bsv = bias_s[c];
                float v = pre_s[0][c][bb] + bsv;
                float m = pre_s[1][c][bb] + bsv;
                float r = pre_s[2][c][bb];
                pv[g] = v; pl[g] = m - r; pu[g] = m + r;
            }
            float iv = sigf(pv[0]), il = sigf(pl[0]), iu = sigf(pu[0]);
            float fv = sigf(pv[1]), fl = sigf(pl[1]), fu = sigf(pu[1]);
            float gv = tanhf(pv[2]), gl = tanhf(pl[2]), gu = tanhf(pu[2]);
            float ov = sigf(pv[3]), ol = sigf(pl[3]), ou = sigf(pu[3]);

            float cv = c_s[0][jj][bb], cl = c_s[1][jj][bb], cu = c_s[2][jj][bb];
            float lo1, hi1, lo2, hi2;
            imul_b(fl, fu, cl, cu, lo1, hi1);
            imul_b(il, iu, gl, gu, lo2, hi2);
            float ncv = fv * cv + iv * gv;
            float ncl = lo1 + lo2, ncu = hi1 + hi2;
            c_s[0][jj][bb] = ncv; c_s[1][jj][bb] = ncl; c_s[2][jj][bb] = ncu;

            float tv = tanhf(ncv), tl = tanhf(ncl), tu = tanhf(ncu);
            float hv = ov * tv, hl, hu;
            imul_b(ol, ou, tl, tu, hl, hu);

            const int j = bid * 2 + jj;
            size_t o = ((size_t)bb * T + t) * H + j;
            out[o] = hv;
            out[(size_t)B * T * H + o] = hl;
            out[2 * (size_t)B * T * H + o] = hu;

            const int nb_ = (t + 1) & 1;
            g_h[nb_][0][bb][j] = hv;
            g_h[nb_][1][bb][j] = 0.5f * (hl + hu);
            g_h[nb_][2][bb][j] = 0.5f * (hu - hl);
        }

        if (t < T - 1) {
            // release writes, arrive early, hide barrier behind x-part(t+1)
            __threadfence();
            __syncthreads();
            unsigned target = 0;
            if (tid == 0) {
                unsigned tk = atomicAdd(&g_tick, 1u);
                target = tk - (tk % NB) + NB;
            }
            xpart(t + 1);
            if (tid == 0) {
                while ((int)(*(volatile unsigned*)&g_tick - target) < 0) {}
            }
            __syncthreads();
            __threadfence();  // gpu-scope fence -> CCTL.IVALL: invalidate L1 so fresh h is read
        }
    }
}

extern "C" void kernel_launch(void* const* d_in, const int* in_sizes, int n_in,
                              void* d_out, int out_size) {
    (void)in_sizes; (void)n_in; (void)out_size;
    const float* x_val = (const float*)d_in[0];
    const float* x_lb  = (const float*)d_in[1];
    const float* x_ub  = (const float*)d_in[2];
    const float* W_ih  = (const float*)d_in[3];
    const float* W_hh  = (const float*)d_in[4];
    const float* b     = (const float*)d_in[5];
    lstm_dp_kernel<<<NB, NT>>>(x_val, x_lb, x_ub, W_ih, W_hh, b, (float*)d_out);
}

// round 3
// speedup vs baseline: 2.8040x; 2.8040x over previous
#include <cuda_runtime.h>
#include <math.h>

typedef unsigned long long ull;

#define B 64
#define T 512
#define D 128
#define H 256
#define NB 128
#define NT 128
#define WST 386   // smem weight row stride (mod 32 == 2 -> conflict-free col-group broadcast)

// Hidden state, double buffered, k-pair packed: [buf][comp v/m/r][q=j/2][b] = float2{h[2q],h[2q+1]}
__device__ ull g_h2[2][3][128][64];
// Pre-transposed x (val/center/radius), k-pair packed: [comp][t][q=k/2][b]
__device__ ull g_x2[3][T][64][64];
// Monotonic grid-barrier ticket (never reset; wrap-safe signed compare)
__device__ unsigned int g_tick = 0;

__device__ __forceinline__ void fma2(ull &acc, ull x, ull w) {
    asm("fma.rn.f32x2 %0, %1, %2, %0;" : "+l"(acc) : "l"(x), "l"(w));
}
__device__ __forceinline__ float red2(ull a) {
    float lo = __uint_as_float((unsigned)a);
    float hi = __uint_as_float((unsigned)(a >> 32));
    return lo + hi;
}
__device__ __forceinline__ float sigf(float x) { return 1.0f / (1.0f + expf(-x)); }
__device__ __forceinline__ void imul_b(float al, float au, float bl, float bu,
                                       float &lo, float &hi) {
    float m1 = al * bl, m2 = al * bu, m3 = au * bl, m4 = au * bu;
    lo = fminf(fminf(m1, m2), fminf(m3, m4));
    hi = fmaxf(fmaxf(m1, m2), fmaxf(m3, m4));
}

// One k-pair: 12 packed FMAs for 4 cols x 3 comps (v,m use w; r uses |w|)
#define STEPK(HV, HM, HR, KO)                                                   \
    do {                                                                        \
        ull _w0 = *(const ull*)(wp0 + (KO)); ull _a0 = *(const ull*)(ap0 + (KO)); \
        fma2(acc0, HV, _w0); fma2(acc1, HM, _w0); fma2(acc2, HR, _a0);          \
        ull _w1 = *(const ull*)(wp1 + (KO)); ull _a1 = *(const ull*)(ap1 + (KO)); \
        fma2(acc3, HV, _w1); fma2(acc4, HM, _w1); fma2(acc5, HR, _a1);          \
        ull _w2 = *(const ull*)(wp2 + (KO)); ull _a2 = *(const ull*)(ap2 + (KO)); \
        fma2(acc6, HV, _w2); fma2(acc7, HM, _w2); fma2(acc8, HR, _a2);          \
        ull _w3 = *(const ull*)(wp3 + (KO)); ull _a3 = *(const ull*)(ap3 + (KO)); \
        fma2(acc9, HV, _w3); fma2(acc10, HM, _w3); fma2(acc11, HR, _a3);        \
    } while (0)

__global__ void __launch_bounds__(NT, 1)
lstm_dp_kernel(const float* __restrict__ x_val, const float* __restrict__ x_lb,
               const float* __restrict__ x_ub, const float* __restrict__ W_ih,
               const float* __restrict__ W_hh, const float* __restrict__ bias,
               float* __restrict__ out) {
    extern __shared__ float sm[];
    float* ws     = sm;                  // [16][WST]  W (hh in k<256, ih in k>=256)
    float* aws    = ws + 16 * WST;       // [16][WST]  |W|
    float* pre    = aws + 16 * WST;      // [3][16][32] (comp, col, b_local)
    float* hout   = pre + 3 * 16 * 32;   // [3][4][32]  h result (v,m,r)
    float* cs     = hout + 3 * 4 * 32;   // [3][4][32]  cell state (val, lb, ub)
    float* bias_s = cs + 3 * 4 * 32;     // [16]

    const int tid  = threadIdx.x;
    const int bid  = blockIdx.x;
    const int cb   = bid >> 1;           // col-block: owns h-cols [4cb, 4cb+4)
    const int bh   = bid & 1;            // batch half: batches [32bh, 32bh+32)
    const int wrp  = tid >> 5;
    const int lane = tid & 31;
    const int cg   = lane >> 3;          // gate index for this thread's 4 cols
    const int bslot = 8 * wrp + (lane & 7);   // local batch 0..31
    const int bgl   = 32 * bh + bslot;        // global batch

    // ---- Prologue ----
    for (int i = tid; i < 16 * 384; i += NT) {
        int c = i / 384, k = i - c * 384;
        int row = (c >> 2) * H + 4 * cb + (c & 3);
        float wv = (k < H) ? W_hh[row * H + k] : W_ih[row * D + (k - H)];
        ws[c * WST + k] = wv;
        aws[c * WST + k] = fabsf(wv);
    }
    if (tid < 16) {
        int row = (tid >> 2) * H + 4 * cb + (tid & 3);
        bias_s[tid] = bias[row];
    }
    for (int i = tid; i < 3 * 4 * 32; i += NT) cs[i] = 0.f;

    // zero h buffer 0 (buf is outermost dim -> first 3*128*64 ulls)
    for (int i = bid * NT + tid; i < 3 * 128 * 64; i += NB * NT)
        ((ull*)g_h2)[i] = 0ULL;

    // transpose x into [comp][t][q][b] k-pair-packed layout (writes coalesced)
    for (int idx = bid * NT + tid; idx < T * 64 * 64; idx += NB * NT) {
        int b = idx & 63;
        int kk = (idx >> 6) & 63;
        int t = idx >> 12;
        int base = (b * T + t) * D + 2 * kk;
        float2 v = *(const float2*)(x_val + base);
        float2 l = *(const float2*)(x_lb + base);
        float2 u = *(const float2*)(x_ub + base);
        float2 m = make_float2(0.5f * (l.x + u.x), 0.5f * (l.y + u.y));
        float2 r = make_float2(0.5f * (u.x - l.x), 0.5f * (u.y - l.y));
        int o = (t * 64 + kk) * 64 + b;
        ((float2*)g_x2)[o] = v;
        ((float2*)g_x2)[T * 64 * 64 + o] = m;
        ((float2*)g_x2)[2 * T * 64 * 64 + o] = r;
    }

    // grid barrier
    __threadfence();
    __syncthreads();
    if (tid == 0) {
        unsigned tk = atomicAdd(&g_tick, 1u);
        unsigned target = tk - (tk % NB) + NB;
        while ((int)(*(volatile unsigned*)&g_tick - target) < 0) {}
    }
    __syncthreads();
    __threadfence();

    // ---- per-thread weight row pointers (4 cols of gate cg) ----
    const float* wp0 = ws + (cg * 4 + 0) * WST;
    const float* wp1 = ws + (cg * 4 + 1) * WST;
    const float* wp2 = ws + (cg * 4 + 2) * WST;
    const float* wp3 = ws + (cg * 4 + 3) * WST;
    const float* ap0 = aws + (cg * 4 + 0) * WST;
    const float* ap1 = aws + (cg * 4 + 1) * WST;
    const float* ap2 = aws + (cg * 4 + 2) * WST;
    const float* ap3 = aws + (cg * 4 + 3) * WST;

    ull acc0 = 0, acc1 = 0, acc2 = 0, acc3 = 0, acc4 = 0, acc5 = 0;
    ull acc6 = 0, acc7 = 0, acc8 = 0, acc9 = 0, acc10 = 0, acc11 = 0;

    const ull* Xv = &g_x2[0][0][0][0] + bgl;
    const ull* Xm = &g_x2[1][0][0][0] + bgl;
    const ull* Xr = &g_x2[2][0][0][0] + bgl;

    auto xpart = [&](int tt) {
        const int tb = tt * 64 * 64;
#pragma unroll 8
        for (int kk = 0; kk < 64; ++kk) {
            ull hv = Xv[tb + kk * 64];
            ull hm = Xm[tb + kk * 64];
            ull hr = Xr[tb + kk * 64];
            STEPK(hv, hm, hr, 256 + 2 * kk);
        }
    };

    xpart(0);

    for (int t = 0; t < T; ++t) {
        const int buf = t & 1;
        // ---- h-side projection (K = 256 -> 128 k-pairs) ----
        {
            const ull* Hv = &g_h2[buf][0][0][0] + bgl;
            const ull* Hm = &g_h2[buf][1][0][0] + bgl;
            const ull* Hr = &g_h2[buf][2][0][0] + bgl;
#pragma unroll 8
            for (int kk = 0; kk < 128; ++kk) {
                ull hv = Hv[kk * 64];
                ull hm = Hm[kk * 64];
                ull hr = Hr[kk * 64];
                STEPK(hv, hm, hr, 2 * kk);
            }
        }
        // ---- dump accumulators to smem ----
        {
            int c0 = cg * 4;
            pre[0 * 512 + (c0 + 0) * 32 + bslot] = red2(acc0);
            pre[1 * 512 + (c0 + 0) * 32 + bslot] = red2(acc1);
            pre[2 * 512 + (c0 + 0) * 32 + bslot] = red2(acc2);
            pre[0 * 512 + (c0 + 1) * 32 + bslot] = red2(acc3);
            pre[1 * 512 + (c0 + 1) * 32 + bslot] = red2(acc4);
            pre[2 * 512 + (c0 + 1) * 32 + bslot] = red2(acc5);
            pre[0 * 512 + (c0 + 2) * 32 + bslot] = red2(acc6);
            pre[1 * 512 + (c0 + 2) * 32 + bslot] = red2(acc7);
            pre[2 * 512 + (c0 + 2) * 32 + bslot] = red2(acc8);
            pre[0 * 512 + (c0 + 3) * 32 + bslot] = red2(acc9);
            pre[1 * 512 + (c0 + 3) * 32 + bslot] = red2(acc10);
            pre[2 * 512 + (c0 + 3) * 32 + bslot] = red2(acc11);
            acc0 = acc1 = acc2 = acc3 = acc4 = acc5 = 0;
            acc6 = acc7 = acc8 = acc9 = acc10 = acc11 = 0;
        }
        __syncthreads();

        // ---- elementwise: one (jc, b_local) per thread ----
        {
            const int jc = tid >> 5, bl = tid & 31;
            float pv[4], pl[4], pu[4];
#pragma unroll
            for (int g = 0; g < 4; ++g) {
                int c = g * 4 + jc;
                float bsv = bias_s[c];
                float v = pre[0 * 512 + c * 32 + bl] + bsv;
                float m = pre[1 * 512 + c * 32 + bl] + bsv;
                float r = pre[2 * 512 + c * 32 + bl];
                pv[g] = v; pl[g] = m - r; pu[g] = m + r;
            }
            float iv = sigf(pv[0]), il = sigf(pl[0]), iu = sigf(pu[0]);
            float fv = sigf(pv[1]), fl = sigf(pl[1]), fu = sigf(pu[1]);
            float gv = tanhf(pv[2]), gl = tanhf(pl[2]), gu = tanhf(pu[2]);
            float ov = sigf(pv[3]), ol = sigf(pl[3]), ou = sigf(pu[3]);

            float cv = cs[0 * 128 + jc * 32 + bl];
            float cl = cs[1 * 128 + jc * 32 + bl];
            float cu = cs[2 * 128 + jc * 32 + bl];
            float lo1, hi1, lo2, hi2;
            imul_b(fl, fu, cl, cu, lo1, hi1);
            imul_b(il, iu, gl, gu, lo2, hi2);
            float ncv = fv * cv + iv * gv;
            float ncl = lo1 + lo2, ncu = hi1 + hi2;
            cs[0 * 128 + jc * 32 + bl] = ncv;
            cs[1 * 128 + jc * 32 + bl] = ncl;
            cs[2 * 128 + jc * 32 + bl] = ncu;

            float tv = tanhf(ncv), tl = tanhf(ncl), tu = tanhf(ncu);
            float hv = ov * tv, hl, hu;
            imul_b(ol, ou, tl, tu, hl, hu);

            hout[0 * 128 + jc * 32 + bl] = hv;              // value
            hout[1 * 128 + jc * 32 + bl] = 0.5f * (hl + hu); // center
            hout[2 * 128 + jc * 32 + bl] = 0.5f * (hu - hl); // radius
        }
        __syncthreads();

        // ---- writes: output (coalesced float4 over 4 cols) + next h buffer ----
        if (tid < 96) {
            const int comp_o = tid >> 5;   // 0=val, 1=lb, 2=ub
            const int bb = tid & 31;
            float4 o4;
            float vv[4];
#pragma unroll
            for (int jcx = 0; jcx < 4; ++jcx) {
                float v = hout[0 * 128 + jcx * 32 + bb];
                float m = hout[1 * 128 + jcx * 32 + bb];
                float r = hout[2 * 128 + jcx * 32 + bb];
                vv[jcx] = (comp_o == 0) ? v : ((comp_o == 1) ? (m - r) : (m + r));
            }
            o4.x = vv[0]; o4.y = vv[1]; o4.z = vv[2]; o4.w = vv[3];
            size_t oidx = (size_t)comp_o * B * T * H +
                          ((size_t)(32 * bh + bb) * T + t) * H + 4 * cb;
            *(float4*)(out + oidx) = o4;
        }
        {
            const int nbuf = (t + 1) & 1;
#pragma unroll
            for (int i = tid; i < 192; i += NT) {
                int comp = i >> 6;
                int rem = i & 63;
                int qq = rem >> 5;
                int bb = rem & 31;
                float v0 = hout[comp * 128 + (2 * qq) * 32 + bb];
                float v1 = hout[comp * 128 + (2 * qq + 1) * 32 + bb];
                float2 p = make_float2(v0, v1);
                g_h2[nbuf][comp][2 * cb + qq][32 * bh + bb] = *(ull*)&p;
            }
        }

        if (t < T - 1) {
            __threadfence();
            __syncthreads();
            unsigned target = 0;
            if (tid == 0) {
                unsigned tk = atomicAdd(&g_tick, 1u);
                target = tk - (tk % NB) + NB;
            }
            xpart(t + 1);  // hide barrier latency behind x-side projection
            if (tid == 0) {
                while ((int)(*(volatile unsigned*)&g_tick - target) < 0) {}
            }
            __syncthreads();
            __threadfence();  // acquire: CCTL.IVALL so fresh h is read next step
        }
    }
}

extern "C" void kernel_launch(void* const* d_in, const int* in_sizes, int n_in,
                              void* d_out, int out_size) {
    (void)in_sizes; (void)n_in; (void)out_size;
    const float* x_val = (const float*)d_in[0];
    const float* x_lb  = (const float*)d_in[1];
    const float* x_ub  = (const float*)d_in[2];
    const float* W_ih  = (const float*)d_in[3];
    const float* W_hh  = (const float*)d_in[4];
    const float* b     = (const float*)d_in[5];
    const int smem_bytes = (16 * WST * 2 + 3 * 16 * 32 + 3 * 4 * 32 * 2 + 16) * 4;
    cudaFuncSetAttribute(lstm_dp_kernel, cudaFuncAttributeMaxDynamicSharedMemorySize,
                         smem_bytes);
    lstm_dp_kernel<<<NB, NT, smem_bytes>>>(x_val, x_lb, x_ub, W_ih, W_hh, b,
                                           (float*)d_out);
}

// round 4
// speedup vs baseline: 4.3078x; 1.5363x over previous
#include <cuda_runtime.h>
#include <math.h>

typedef unsigned long long ull;

#define B 64
#define T 512
#define D 128
#define H 256
#define NB 128
#define NT 256
#define WST 388   // smem weight row stride (floats): 1552B, %128=16 -> 4 consecutive rows on distinct banks, 16B aligned
#define PST 33    // pre[] column stride (conflict-free gate-strided access)

#define ABSMASK 0x7fffffff7fffffffULL

// Hidden state, double buffered, k-quad packed: [buf][comp v/m/r][qq=j/4][b]
__device__ ulonglong2 g_h4[2][3][64][64];
// Pre-transposed x (val/center/radius), k-quad packed: [comp][t][qq=k/4][b]
__device__ ulonglong2 g_x4[3][T][32][64];
// Monotonic grid-barrier ticket (never reset; wrap-safe signed compare)
__device__ unsigned int g_tick = 0;

__device__ __forceinline__ void fma2(ull &acc, ull x, ull w) {
    asm("fma.rn.f32x2 %0, %1, %2, %0;" : "+l"(acc) : "l"(x), "l"(w));
}
__device__ __forceinline__ float red2(ull a) {
    float lo = __uint_as_float((unsigned)a);
    float hi = __uint_as_float((unsigned)(a >> 32));
    return lo + hi;
}
__device__ __forceinline__ ulonglong2 ldcg2(const ulonglong2* p) {
    ulonglong2 r;
    asm volatile("ld.global.cg.v2.u64 {%0,%1}, [%2];"
                 : "=l"(r.x), "=l"(r.y) : "l"(p));
    return r;
}
__device__ __forceinline__ float sigf(float x) {
    return __fdividef(1.0f, 1.0f + __expf(-x));
}
__device__ __forceinline__ float tanh_f(float x) {
    return fmaf(2.0f, sigf(2.0f * x), -1.0f);
}
__device__ __forceinline__ void imul_b(float al, float au, float bl, float bu,
                                       float &lo, float &hi) {
    float m1 = al * bl, m2 = al * bu, m3 = au * bl, m4 = au * bu;
    lo = fminf(fminf(m1, m2), fminf(m3, m4));
    hi = fmaxf(fmaxf(m1, m2), fmaxf(m3, m4));
}

// One k-quad (4 k floats = 2 f32x2 pairs) for 4 cols x 3 comps.
// 4 LDS.128 + 24 FFMA2 + 8 packed-AND (alu pipe).
#define UNIT(HV, HM, HR, KO)                                                    \
    do {                                                                        \
        ulonglong2 w; ull aw;                                                   \
        w = *(const ulonglong2*)(wp0 + (KO));                                   \
        fma2(a0v, (HV).x, w.x); fma2(a0m, (HM).x, w.x);                         \
        aw = w.x & ABSMASK; fma2(a0r, (HR).x, aw);                              \
        fma2(a0v, (HV).y, w.y); fma2(a0m, (HM).y, w.y);                         \
        aw = w.y & ABSMASK; fma2(a0r, (HR).y, aw);                              \
        w = *(const ulonglong2*)(wp1 + (KO));                                   \
        fma2(a1v, (HV).x, w.x); fma2(a1m, (HM).x, w.x);                         \
        aw = w.x & ABSMASK; fma2(a1r, (HR).x, aw);                              \
        fma2(a1v, (HV).y, w.y); fma2(a1m, (HM).y, w.y);                         \
        aw = w.y & ABSMASK; fma2(a1r, (HR).y, aw);                              \
        w = *(const ulonglong2*)(wp2 + (KO));                                   \
        fma2(a2v, (HV).x, w.x); fma2(a2m, (HM).x, w.x);                         \
        aw = w.x & ABSMASK; fma2(a2r, (HR).x, aw);                              \
        fma2(a2v, (HV).y, w.y); fma2(a2m, (HM).y, w.y);                         \
        aw = w.y & ABSMASK; fma2(a2r, (HR).y, aw);                              \
        w = *(const ulonglong2*)(wp3 + (KO));                                   \
        fma2(a3v, (HV).x, w.x); fma2(a3m, (HM).x, w.x);                         \
        aw = w.x & ABSMASK; fma2(a3r, (HR).x, aw);                              \
        fma2(a3v, (HV).y, w.y); fma2(a3m, (HM).y, w.y);                         \
        aw = w.y & ABSMASK; fma2(a3r, (HR).y, aw);                              \
    } while (0)

__global__ void __launch_bounds__(NT, 1)
lstm_dp_kernel(const float* __restrict__ x_val, const float* __restrict__ x_lb,
               const float* __restrict__ x_ub, const float* __restrict__ W_ih,
               const float* __restrict__ W_hh, const float* __restrict__ bias,
               float* __restrict__ out) {
    extern __shared__ float sm[];
    float* ws      = sm;                    // [16][WST] permuted rows: smem row 4*j+g
    float* scratch = ws + 16 * WST;         // [12][128] K-split partials
    float* pre     = scratch + 12 * 128;    // [3][16][PST]
    float* hout    = pre + 3 * 16 * PST;    // [3][4][32] (v, center, radius)
    float* cs      = hout + 384;            // [3][4][32] cell state (val, lb, ub)
    float* bias_s  = cs + 384;              // [16]

    const int tid  = threadIdx.x;
    const int bid  = blockIdx.x;
    const int cb   = bid >> 1;              // col-block: h-cols [4cb, 4cb+4)
    const int bh   = bid & 1;               // batch half
    const int warp = tid >> 5;
    const int lane = tid & 31;
    const int kh   = warp >> 2;             // K-half (0: low, 1: high)
    const int wl   = warp & 3;
    const int cg   = lane >> 3;             // gate index
    const int bslot = 8 * wl + (lane & 7);  // local batch 0..31
    const int bgl   = 32 * bh + bslot;      // global batch
    const int t128  = tid & 127;

    // ---- Prologue ----
    for (int i = tid; i < 16 * 384; i += NT) {
        int c = i / 384, k = i - c * 384;
        int j = c >> 2, g = c & 3;          // smem row c = 4*j + g
        int row = g * H + 4 * cb + j;
        ws[c * WST + k] = (k < H) ? W_hh[row * H + k] : W_ih[row * D + (k - H)];
    }
    if (tid < 16) bias_s[tid] = bias[(tid >> 2) * H + 4 * cb + (tid & 3)];
    for (int i = tid; i < 384; i += NT) cs[i] = 0.f;

    // zero h buffer 0
    for (int i = bid * NT + tid; i < 3 * 64 * 64; i += NB * NT) {
        ulonglong2 z; z.x = 0; z.y = 0;
        ((ulonglong2*)g_h4)[i] = z;
    }

    // transpose x into [comp][t][qq][b] k-quad layout (writes coalesced)
    for (int i = bid * NT + tid; i < T * 32 * 64; i += NB * NT) {
        int b = i & 63, qq = (i >> 6) & 31, t = i >> 11;
        int base = (b * T + t) * D + 4 * qq;
        float4 v = *(const float4*)(x_val + base);
        float4 l = *(const float4*)(x_lb + base);
        float4 u = *(const float4*)(x_ub + base);
        float4 m, r;
        m.x = 0.5f * (l.x + u.x); m.y = 0.5f * (l.y + u.y);
        m.z = 0.5f * (l.z + u.z); m.w = 0.5f * (l.w + u.w);
        r.x = 0.5f * (u.x - l.x); r.y = 0.5f * (u.y - l.y);
        r.z = 0.5f * (u.z - l.z); r.w = 0.5f * (u.w - l.w);
        int o = (t * 32 + qq) * 64 + b;
        ((float4*)g_x4)[o] = v;
        ((float4*)g_x4)[T * 32 * 64 + o] = m;
        ((float4*)g_x4)[2 * T * 32 * 64 + o] = r;
    }

    // grid barrier
    __threadfence();
    __syncthreads();
    if (tid == 0) {
        unsigned tk = atomicAdd(&g_tick, 1u);
        unsigned target = tk - (tk % NB) + NB;
        while ((int)(*(volatile unsigned*)&g_tick - target) < 0) {}
    }
    __syncthreads();
    __threadfence();

    // weight row pointers: row for (gate cg, col j) lives at smem row 4*j+cg
    const float* wp0 = ws + (0 + cg) * WST;
    const float* wp1 = ws + (4 + cg) * WST;
    const float* wp2 = ws + (8 + cg) * WST;
    const float* wp3 = ws + (12 + cg) * WST;

    ull a0v = 0, a0m = 0, a0r = 0, a1v = 0, a1m = 0, a1r = 0;
    ull a2v = 0, a2m = 0, a2r = 0, a3v = 0, a3m = 0, a3r = 0;

    auto xpart = [&](int tt) {
        const ulonglong2* Xv = &g_x4[0][tt][0][0] + bgl;
        const ulonglong2* Xm = &g_x4[1][tt][0][0] + bgl;
        const ulonglong2* Xr = &g_x4[2][tt][0][0] + bgl;
        const int q0 = 16 * kh;
#pragma unroll 4
        for (int u = 0; u < 16; ++u) {
            int qq = q0 + u;
            ulonglong2 xv = ldcg2(Xv + qq * 64);
            ulonglong2 xm = ldcg2(Xm + qq * 64);
            ulonglong2 xr = ldcg2(Xr + qq * 64);
            UNIT(xv, xm, xr, 256 + 4 * qq);
        }
    };

    xpart(0);

    for (int t = 0; t < T; ++t) {
        const int buf = t & 1;
        // ---- h-side projection: this K-half's 32 k-quads ----
        {
            const ulonglong2* Hv = &g_h4[buf][0][0][0] + bgl;
            const ulonglong2* Hm = &g_h4[buf][1][0][0] + bgl;
            const ulonglong2* Hr = &g_h4[buf][2][0][0] + bgl;
            const int q0 = 32 * kh;
#pragma unroll 4
            for (int u = 0; u < 32; ++u) {
                int qq = q0 + u;
                ulonglong2 hv = ldcg2(Hv + qq * 64);
                ulonglong2 hm = ldcg2(Hm + qq * 64);
                ulonglong2 hr = ldcg2(Hr + qq * 64);
                UNIT(hv, hm, hr, 4 * qq);
            }
        }
        // ---- K-split combine ----
        {
            float p0 = red2(a0v), p1 = red2(a0m), p2 = red2(a0r);
            float p3 = red2(a1v), p4 = red2(a1m), p5 = red2(a1r);
            float p6 = red2(a2v), p7 = red2(a2m), p8 = red2(a2r);
            float p9 = red2(a3v), p10 = red2(a3m), p11 = red2(a3r);
            a0v = a0m = a0r = a1v = a1m = a1r = 0;
            a2v = a2m = a2r = a3v = a3m = a3r = 0;
            if (kh) {
                scratch[0 * 128 + t128] = p0;  scratch[1 * 128 + t128] = p1;
                scratch[2 * 128 + t128] = p2;  scratch[3 * 128 + t128] = p3;
                scratch[4 * 128 + t128] = p4;  scratch[5 * 128 + t128] = p5;
                scratch[6 * 128 + t128] = p6;  scratch[7 * 128 + t128] = p7;
                scratch[8 * 128 + t128] = p8;  scratch[9 * 128 + t128] = p9;
                scratch[10 * 128 + t128] = p10; scratch[11 * 128 + t128] = p11;
            }
            __syncthreads();
            if (!kh) {
                const int c0 = cg * 4;
                pre[0 * 528 + (c0 + 0) * PST + bslot] = p0 + scratch[0 * 128 + t128];
                pre[1 * 528 + (c0 + 0) * PST + bslot] = p1 + scratch[1 * 128 + t128];
                pre[2 * 528 + (c0 + 0) * PST + bslot] = p2 + scratch[2 * 128 + t128];
                pre[0 * 528 + (c0 + 1) * PST + bslot] = p3 + scratch[3 * 128 + t128];
                pre[1 * 528 + (c0 + 1) * PST + bslot] = p4 + scratch[4 * 128 + t128];
                pre[2 * 528 + (c0 + 1) * PST + bslot] = p5 + scratch[5 * 128 + t128];
                pre[0 * 528 + (c0 + 2) * PST + bslot] = p6 + scratch[6 * 128 + t128];
                pre[1 * 528 + (c0 + 2) * PST + bslot] = p7 + scratch[7 * 128 + t128];
                pre[2 * 528 + (c0 + 2) * PST + bslot] = p8 + scratch[8 * 128 + t128];
                pre[0 * 528 + (c0 + 3) * PST + bslot] = p9 + scratch[9 * 128 + t128];
                pre[1 * 528 + (c0 + 3) * PST + bslot] = p10 + scratch[10 * 128 + t128];
                pre[2 * 528 + (c0 + 3) * PST + bslot] = p11 + scratch[11 * 128 + t128];
            }
            __syncthreads();
        }

        // ---- activations: 512 (col,b) pairs over 256 threads ----
#pragma unroll
        for (int i = tid; i < 512; i += NT) {
            int c = i >> 5, b = i & 31;
            float bs = bias_s[c];
            int o = c * PST + b;
            float v = pre[o] + bs;
            float m = pre[528 + o] + bs;
            float r = pre[1056 + o];
            float l = m - r, u2 = m + r;
            if ((c >> 2) == 2) { v = tanh_f(v); l = tanh_f(l); u2 = tanh_f(u2); }
            else               { v = sigf(v);   l = sigf(l);   u2 = sigf(u2); }
            pre[o] = v; pre[528 + o] = l; pre[1056 + o] = u2;
        }
        __syncthreads();

        // ---- interval combine: one (jc, b) per thread (tid < 128) ----
        if (tid < 128) {
            const int jc = tid >> 5, bl = tid & 31;
            int o0 = (0 + jc) * PST + bl;
            int o1 = (4 + jc) * PST + bl;
            int o2 = (8 + jc) * PST + bl;
            int o3 = (12 + jc) * PST + bl;
            float iv = pre[o0], il = pre[528 + o0], iu = pre[1056 + o0];
            float fv = pre[o1], fl = pre[528 + o1], fu = pre[1056 + o1];
            float gv = pre[o2], gl = pre[528 + o2], gu = pre[1056 + o2];
            float ov = pre[o3], ol = pre[528 + o3], ou = pre[1056 + o3];

            float cv = cs[0 * 128 + jc * 32 + bl];
            float cl = cs[1 * 128 + jc * 32 + bl];
            float cu = cs[2 * 128 + jc * 32 + bl];
            float lo1, hi1, lo2, hi2;
            imul_b(fl, fu, cl, cu, lo1, hi1);
            imul_b(il, iu, gl, gu, lo2, hi2);
            float ncv = fv * cv + iv * gv;
            float ncl = lo1 + lo2, ncu = hi1 + hi2;
            cs[0 * 128 + jc * 32 + bl] = ncv;
            cs[1 * 128 + jc * 32 + bl] = ncl;
            cs[2 * 128 + jc * 32 + bl] = ncu;

            float tv = tanh_f(ncv), tl = tanh_f(ncl), tu = tanh_f(ncu);
            float hv = ov * tv, hl, hu;
            imul_b(ol, ou, tl, tu, hl, hu);

            hout[0 * 128 + jc * 32 + bl] = hv;
            hout[1 * 128 + jc * 32 + bl] = 0.5f * (hl + hu);
            hout[2 * 128 + jc * 32 + bl] = 0.5f * (hu - hl);
        }
        __syncthreads();

        // ---- writes: out (float4) + next h buffer (ull2) ----
        if (tid < 96) {
            const int comp = tid >> 5;   // 0=val, 1=(lb|center), 2=(ub|radius)
            const int bb = tid & 31;
            float f0 = hout[comp * 128 + 0 * 32 + bb];
            float f1 = hout[comp * 128 + 1 * 32 + bb];
            float f2 = hout[comp * 128 + 2 * 32 + bb];
            float f3 = hout[comp * 128 + 3 * 32 + bb];
            // h state: (v, center, radius) direct
            ulonglong2 p;
            p.x = (ull)__float_as_uint(f0) | ((ull)__float_as_uint(f1) << 32);
            p.y = (ull)__float_as_uint(f2) | ((ull)__float_as_uint(f3) << 32);
            g_h4[(t + 1) & 1][comp][cb][32 * bh + bb] = p;
            // out: comp 0 = val, 1 = lb = m-r, 2 = ub = m+r
            float4 o4;
            if (comp == 0) {
                o4.x = f0; o4.y = f1; o4.z = f2; o4.w = f3;
            } else {
                float sgn = (comp == 1) ? -1.f : 1.f;
                o4.x = fmaf(sgn, hout[2 * 128 + 0 * 32 + bb], hout[128 + 0 * 32 + bb]);
                o4.y = fmaf(sgn, hout[2 * 128 + 1 * 32 + bb], hout[128 + 1 * 32 + bb]);
                o4.z = fmaf(sgn, hout[2 * 128 + 2 * 32 + bb], hout[128 + 2 * 32 + bb]);
                o4.w = fmaf(sgn, hout[2 * 128 + 3 * 32 + bb], hout[128 + 3 * 32 + bb]);
            }
            size_t oidx = (size_t)comp * B * T * H +
                          ((size_t)(32 * bh + bb) * T + t) * H + 4 * cb;
            *(float4*)(out + oidx) = o4;
        }

        if (t < T - 1) {
            __threadfence();          // release h writes
            __syncthreads();
            unsigned target = 0;
            if (tid == 0) {
                unsigned tk = atomicAdd(&g_tick, 1u);
                target = tk - (tk % NB) + NB;
            }
            xpart(t + 1);             // hide barrier behind x-side projection
            if (tid == 0) {
                while ((int)(*(volatile unsigned*)&g_tick - target) < 0) {}
            }
            __syncthreads();
            __threadfence();          // acquire
        }
    }
}

extern "C" void kernel_launch(void* const* d_in, const int* in_sizes, int n_in,
                              void* d_out, int out_size) {
    (void)in_sizes; (void)n_in; (void)out_size;
    const float* x_val = (const float*)d_in[0];
    const float* x_lb  = (const float*)d_in[1];
    const float* x_ub  = (const float*)d_in[2];
    const float* W_ih  = (const float*)d_in[3];
    const float* W_hh  = (const float*)d_in[4];
    const float* b     = (const float*)d_in[5];
    const int smem_bytes = (16 * WST + 12 * 128 + 3 * 16 * PST + 384 + 384 + 16) * 4;
    lstm_dp_kernel<<<NB, NT, smem_bytes>>>(x_val, x_lb, x_ub, W_ih, W_hh, b,
                                           (float*)d_out);
}